// round 16
// baseline (speedup 1.0000x reference)
#include <cuda_runtime.h>
#include <cuda_fp16.h>
#include <cstdint>
#include <cstring>

#define Nn 50000
#define Ee 800000
#define Gg 2048
#define Hh 128

extern __shared__ char dyn_smem[];

// ---------------- device scratch ----------
__device__ uint32_t g_Pa16[Nn * 64];   // fp16x2: nf @ e_w1[0:128]
__device__ uint32_t g_Pb16[Nn * 64];   // fp16x2: nf @ e_w1[128:256]
__device__ uint32_t g_Qb16[Gg * 64];   // fp16x2: lat @ e_w1[256:262] + e_b1
__device__ float    g_Pc[Nn * Hh];     // fp32:   nf @ n_w1[0:128] + n_b1
__device__ uint32_t g_agg16[Nn * 64];  // fp16x2 scatter-sum accumulator
__device__ int      g_cnt[Nn];         // per-node edge count

__device__ __forceinline__ float silu_f(float x) {
    float t;
    asm("tanh.approx.f32 %0, %1;" : "=f"(t) : "f"(0.5f * x));
    return 0.5f * x * (1.0f + t);
}

__device__ __forceinline__ uint32_t pack_h2(float v0, float v1) {
    __half2 h = __floats2half2_rn(v0, v1);
    uint32_t u;
    memcpy(&u, &h, 4);
    return u;
}

__device__ __forceinline__ __half2 h2bits(uint32_t u) {
    __half2 h; memcpy(&h, &u, 4); return h;
}
__device__ __forceinline__ uint32_t bitsh2(__half2 h) {
    uint32_t u; memcpy(&u, &h, 4); return u;
}

__device__ __forceinline__ __half2 silu_h2(__half2 x) {
    __half2 h = __hmul2(x, __float2half2_rn(0.5f));
    uint32_t hb = bitsh2(h), tb;
    asm("tanh.approx.f16x2 %0, %1;" : "=r"(tb) : "r"(hb));
    __half2 t = h2bits(tb);
    return __hfma2(h, t, h);
}

__device__ __forceinline__ void mma16816h(float* d, const uint32_t* a, const uint32_t* b) {
    asm volatile(
        "mma.sync.aligned.m16n8k16.row.col.f32.f16.f16.f32 "
        "{%0,%1,%2,%3}, {%4,%5,%6,%7}, {%8,%9}, {%0,%1,%2,%3};"
        : "+f"(d[0]), "+f"(d[1]), "+f"(d[2]), "+f"(d[3])
        : "r"(a[0]), "r"(a[1]), "r"(a[2]), "r"(a[3]), "r"(b[0]), "r"(b[1]));
}

__device__ __forceinline__ void ldsm_x4(uint32_t* r, uint32_t saddr) {
    asm volatile("ldmatrix.sync.aligned.m8n8.x4.shared.b16 {%0,%1,%2,%3}, [%4];"
        : "=r"(r[0]), "=r"(r[1]), "=r"(r[2]), "=r"(r[3]) : "r"(saddr));
}
__device__ __forceinline__ void ldsm_x2(uint32_t* r, uint32_t saddr) {
    asm volatile("ldmatrix.sync.aligned.m8n8.x2.shared.b16 {%0,%1}, [%2];"
        : "=r"(r[0]), "=r"(r[1]) : "r"(saddr));
}

__device__ __forceinline__ void red4_h2(uint32_t* p, uint32_t a, uint32_t b,
                                        uint32_t c, uint32_t d) {
    asm volatile("red.global.add.noftz.v4.f16x2 [%0], {%1, %2, %3, %4};"
                 :: "l"(p), "r"(a), "r"(b), "r"(c), "r"(d) : "memory");
}

#define PWS 68   // plane word-stride per row (64 pair-words + 4 pad)

// ---------------------------------------------------------------------------
// Kernel 1: persistent Pa/Pb (fp16) + Pc (fp32) + Qb (fp16) precompute
// + zero agg/cnt. ldmatrix fragment loads.
// ---------------------------------------------------------------------------
#define P_B0  0
#define P_B1  8704
#define P_B2  17408
#define P_A   26112
#define P_NB1 34816
#define PREP_SMEM_BYTES ((P_NB1 + 128) * 4)   // 139,776 B
#define PREP_NTILES ((Nn + 127) / 128)         // 391

__launch_bounds__(512, 1)
__global__ void prep_node_kernel(const float* __restrict__ nf,
                                 const float* __restrict__ e_w1,
                                 const float* __restrict__ n_w1,
                                 const float* __restrict__ n_b1,
                                 const float* __restrict__ lat,
                                 const float* __restrict__ e_b1)
{
    uint32_t* smw = (uint32_t*)dyn_smem;
    uint32_t* Bp[3] = {smw + P_B0, smw + P_B1, smw + P_B2};
    uint32_t* A   = smw + P_A;
    float*    NB1 = (float*)(smw + P_NB1);

    const int tid  = threadIdx.x;
    const int wid  = tid >> 5;
    const int lane = tid & 31;
    const int gid  = lane >> 2;
    const int tig  = lane & 3;

    // folded prep_graph: Qb = lat @ e_w1[256:262] + e_b1 -> fp16x2
    for (int idx = blockIdx.x * 512 + tid; idx < Gg * 64; idx += gridDim.x * 512) {
        int g = idx >> 6, c0 = (idx & 63) * 2;
        float a0 = e_b1[c0], a1 = e_b1[c0 + 1];
#pragma unroll
        for (int k = 0; k < 6; k++) {
            float lv = lat[g * 6 + k];
            a0 += lv * e_w1[(256 + k) * 128 + c0];
            a1 += lv * e_w1[(256 + k) * 128 + c0 + 1];
        }
        g_Qb16[idx] = pack_h2(a0, a1);
    }

    if (tid < 128) NB1[tid] = n_b1[tid];
    for (int blk = 0; blk < 3; blk++) {
        const float* bsrc = (blk == 0) ? e_w1
                          : (blk == 1) ? (e_w1 + 128 * 128)
                                       : n_w1;
        uint32_t* B = Bp[blk];
        for (int idx = tid; idx < 8192; idx += 512) {
            int n = idx >> 6, p = idx & 63, k0 = p << 1;
            B[n * PWS + p] = pack_h2(bsrc[k0 * 128 + n], bsrc[(k0 + 1) * 128 + n]);
        }
    }

    const int rg  = wid >> 1;
    const int nfh = wid & 1;
    const int m1  = rg * 16 + gid;

    uint32_t aaddr, baddr0[3];
    const uint32_t jstride = 8u * (PWS * 4);
    {
        int lsub = lane >> 3;
        int arow = rg * 16 + (lsub & 1) * 8 + (lane & 7);
        aaddr = (uint32_t)__cvta_generic_to_shared(A)
              + arow * (PWS * 4) + (lsub >> 1) * 16;
        int brow = nfh * 64 + (lane & 7);
        uint32_t boff = brow * (PWS * 4) + (lsub & 1) * 16;
        for (int blk = 0; blk < 3; blk++)
            baddr0[blk] = (uint32_t)__cvta_generic_to_shared(Bp[blk]) + boff;
    }

    for (int tile = blockIdx.x; tile < PREP_NTILES; tile += gridDim.x) {
        const int row0 = tile * 128;
        __syncthreads();
        if (tid < 128 && row0 + tid < Nn) g_cnt[row0 + tid] = 0;
        for (int idx = tid; idx < 8192; idx += 512) {
            int m = idx >> 6, p = idx & 63, c0 = p << 1;
            int row = row0 + m;
            float v0 = 0.0f, v1 = 0.0f;
            if (row < Nn) {
                const float2 v = *(const float2*)(nf + row * 128 + c0);
                v0 = v.x; v1 = v.y;
                g_agg16[row * 64 + p] = 0u;
            }
            A[m * PWS + p] = pack_h2(v0, v1);
        }
        __syncthreads();

        const int row1 = row0 + m1, row2 = row1 + 8;
        for (int blk = 0; blk < 3; blk++) {
            float acc[8][4];
#pragma unroll
            for (int j = 0; j < 8; j++)
#pragma unroll
                for (int q = 0; q < 4; q++) acc[j][q] = 0.0f;

#pragma unroll
            for (int ks = 0; ks < 8; ks++) {
                uint32_t a[4];
                ldsm_x4(a, aaddr + ks * 32);
#pragma unroll
                for (int j = 0; j < 8; j++) {
                    uint32_t b[2];
                    ldsm_x2(b, baddr0[blk] + j * jstride + ks * 32);
                    mma16816h(acc[j], a, b);
                }
            }

            if (blk < 2) {
                uint32_t* dst16 = (blk == 0) ? g_Pa16 : g_Pb16;
#pragma unroll
                for (int j = 0; j < 8; j++) {
                    const int col = (nfh * 8 + j) * 8 + tig * 2;
                    const int pw = col >> 1;
                    if (row1 < Nn) dst16[row1 * 64 + pw] = pack_h2(acc[j][0], acc[j][1]);
                    if (row2 < Nn) dst16[row2 * 64 + pw] = pack_h2(acc[j][2], acc[j][3]);
                }
            } else {
#pragma unroll
                for (int j = 0; j < 8; j++) {
                    const int col = (nfh * 8 + j) * 8 + tig * 2;
                    float b0 = NB1[col], b1 = NB1[col + 1];
                    if (row1 < Nn)
                        *(float2*)(g_Pc + row1 * 128 + col) =
                            make_float2(acc[j][0] + b0, acc[j][1] + b1);
                    if (row2 < Nn)
                        *(float2*)(g_Pc + row2 * 128 + col) =
                            make_float2(acc[j][2] + b0, acc[j][3] + b1);
                }
            }
        }
    }
}

// ---------------------------------------------------------------------------
// Kernel 3: fused edge pipeline. 128 edges/tile, 256 threads, 2 CTAs/SM.
// Phase A: line-coalesced gather; MMA: ldmatrix;
// epilogue: quad-transpose -> red.v4.f16x2 (16B per op, half the REDG ops).
// ---------------------------------------------------------------------------
#define TILE_M 128
#define EDGE_NTILES (Ee / TILE_M)      // 6250

#define O_SRC   0
#define O_DST   128
#define O_GS    256
#define O_FDS   384
#define O_A     768
#define O_B     (O_A + 128 * PWS)
#define EDGE_SMEM_BYTES ((O_B + 128 * PWS) * 4)   // 72,704 B

__launch_bounds__(256, 2)
__global__ void edge_kernel(const float* __restrict__ frac_diff,
                            const int*   __restrict__ ei,
                            const int*   __restrict__ e2g,
                            const float* __restrict__ e_w1,
                            const float* __restrict__ e_w2,
                            const float* __restrict__ e_b2)
{
    uint32_t* smw = (uint32_t*)dyn_smem;
    int*   srcs = (int*)(smw + O_SRC);
    int*   dsts = (int*)(smw + O_DST);
    int*   gs   = (int*)(smw + O_GS);
    float* fds  = (float*)(smw + O_FDS);
    uint32_t* A = smw + O_A;
    uint32_t* B = smw + O_B;

    const int tid  = threadIdx.x;
    const int wid  = tid >> 5;
    const int lane = tid & 31;
    const int gid  = lane >> 2;
    const int tig  = lane & 3;
    const int wr   = wid >> 2;
    const int wc   = wid & 3;

    uint32_t b2h[4];
#pragma unroll
    for (int nfr = 0; nfr < 4; nfr++) {
        const int c0 = wc * 32 + nfr * 8 + tig * 2;
        b2h[nfr] = pack_h2(e_b2[c0], e_b2[c0 + 1]);
    }

    const int wordpos = (lane & 15) * 4;
    const int rsel    = lane >> 4;
    uint32_t w1dc[3][4];
#pragma unroll
    for (int k = 0; k < 3; k++)
#pragma unroll
        for (int j = 0; j < 4; j++) {
            int c = (wordpos + j) * 2;
            w1dc[k][j] = pack_h2(e_w1[(262 + k) * 128 + c],
                                 e_w1[(262 + k) * 128 + c + 1]);
        }

    for (int idx = tid; idx < 8192; idx += 256) {
        int n = idx >> 6, p = idx & 63, k0 = p << 1;
        B[n * PWS + p] = pack_h2(e_w2[k0 * 128 + n], e_w2[(k0 + 1) * 128 + n]);
    }

    uint32_t aaddr[4], baddr[4];
    {
        uint32_t A_s = (uint32_t)__cvta_generic_to_shared(A);
        uint32_t B_s = (uint32_t)__cvta_generic_to_shared(B);
        int lsub = lane >> 3;
#pragma unroll
        for (int mf = 0; mf < 4; mf++) {
            int arow = wr * 64 + mf * 16 + (lsub & 1) * 8 + (lane & 7);
            aaddr[mf] = A_s + arow * (PWS * 4) + (lsub >> 1) * 16;
        }
        int bsub = lsub & 1;
#pragma unroll
        for (int nfr = 0; nfr < 4; nfr++) {
            int brow = wc * 32 + nfr * 8 + (lane & 7);
            baddr[nfr] = B_s + brow * (PWS * 4) + bsub * 16;
        }
    }

    for (int tile = blockIdx.x; tile < EDGE_NTILES; tile += gridDim.x) {
        __syncthreads();
        const int e0 = tile * TILE_M;
        if (tid < 128) {
            int e = e0 + tid;
            int s = ei[e];
            srcs[tid] = s;
            dsts[tid] = ei[Ee + e];
            gs[tid]   = e2g[e];
            atomicAdd(&g_cnt[s], 1);
        }
        for (int i = tid; i < 384; i += 256) fds[i] = frac_diff[e0 * 3 + i];
        __syncthreads();

        // Phase A: line-coalesced gather + h2 combine + silu
#pragma unroll
        for (int it = 0; it < 8; it++) {
            const int m = wid * 16 + it * 2 + rsel;
            const int sA = srcs[m], dAi = dsts[m], gA = gs[m];
            const __half2 f0h = __float2half2_rn(fds[m * 3 + 0]);
            const __half2 f1h = __float2half2_rn(fds[m * 3 + 1]);
            const __half2 f2h = __float2half2_rn(fds[m * 3 + 2]);
            uint4 pa = *(const uint4*)(g_Pa16 + sA * 64 + wordpos);
            uint4 pb = *(const uint4*)(g_Pb16 + dAi * 64 + wordpos);
            uint4 qb = *(const uint4*)(g_Qb16 + gA * 64 + wordpos);
            uint32_t paw[4] = {pa.x, pa.y, pa.z, pa.w};
            uint32_t pbw[4] = {pb.x, pb.y, pb.z, pb.w};
            uint32_t qbw[4] = {qb.x, qb.y, qb.z, qb.w};
            uint32_t ow[4];
#pragma unroll
            for (int j = 0; j < 4; j++) {
                __half2 x = __hadd2(h2bits(paw[j]), h2bits(pbw[j]));
                x = __hadd2(x, h2bits(qbw[j]));
                x = __hfma2(f0h, h2bits(w1dc[0][j]), x);
                x = __hfma2(f1h, h2bits(w1dc[1][j]), x);
                x = __hfma2(f2h, h2bits(w1dc[2][j]), x);
                ow[j] = bitsh2(silu_h2(x));
            }
            uint4 outw;
            outw.x = ow[0]; outw.y = ow[1]; outw.z = ow[2]; outw.w = ow[3];
            *(uint4*)(A + m * PWS + wordpos) = outw;
        }
        __syncthreads();

        // MMA
        float acc[4][4][4];
#pragma unroll
        for (int mf = 0; mf < 4; mf++)
#pragma unroll
            for (int nfr = 0; nfr < 4; nfr++)
#pragma unroll
                for (int q = 0; q < 4; q++) acc[mf][nfr][q] = 0.0f;

#pragma unroll
        for (int ks = 0; ks < 8; ks++) {
            uint32_t b[4][2];
#pragma unroll
            for (int nfr = 0; nfr < 4; nfr++)
                ldsm_x2(b[nfr], baddr[nfr] + ks * 32);
#pragma unroll
            for (int mf = 0; mf < 4; mf++) {
                uint32_t a[4];
                ldsm_x4(a, aaddr[mf] + ks * 32);
#pragma unroll
                for (int nfr = 0; nfr < 4; nfr++)
                    mma16816h(acc[mf][nfr], a, b[nfr]);
            }
        }

        // Epilogue: h2 bias+silu, 4x4 quad transpose, red.v4.f16x2 (16B)
#pragma unroll
        for (int mf = 0; mf < 4; mf++) {
            const int m1 = wr * 64 + mf * 16 + gid;
            const int rowm = (tig & 1) ? (m1 + 8) : m1;
            uint32_t* dstrow = g_agg16 + srcs[rowm] * 64 + wc * 16;
#pragma unroll
            for (int half = 0; half < 2; half++) {
                uint32_t x[4];
#pragma unroll
                for (int q = 0; q < 2; q++) {
                    const int nfr = half * 2 + q;
                    __half2 hA = __floats2half2_rn(acc[mf][nfr][0], acc[mf][nfr][1]);
                    __half2 hB = __floats2half2_rn(acc[mf][nfr][2], acc[mf][nfr][3]);
                    hA = silu_h2(__hadd2(hA, h2bits(b2h[nfr])));
                    hB = silu_h2(__hadd2(hB, h2bits(b2h[nfr])));
                    x[q * 2 + 0] = bitsh2(hA);
                    x[q * 2 + 1] = bitsh2(hB);
                }
                // 4x4 transpose across quad (tig)
                uint32_t send, got;
                send = (tig & 1) ? x[0] : x[1];
                got = __shfl_xor_sync(0xFFFFFFFFu, send, 1);
                if (tig & 1) x[0] = got; else x[1] = got;
                send = (tig & 1) ? x[2] : x[3];
                got = __shfl_xor_sync(0xFFFFFFFFu, send, 1);
                if (tig & 1) x[2] = got; else x[3] = got;
                send = (tig & 2) ? x[0] : x[2];
                got = __shfl_xor_sync(0xFFFFFFFFu, send, 2);
                if (tig & 2) x[0] = got; else x[2] = got;
                send = (tig & 2) ? x[1] : x[3];
                got = __shfl_xor_sync(0xFFFFFFFFu, send, 2);
                if (tig & 2) x[1] = got; else x[3] = got;
                const int nb = half * 2 + (tig >> 1);
                red4_h2(dstrow + nb * 4, x[0], x[1], x[2], x[3]);
            }
        }
    }
}

// ---------------------------------------------------------------------------
// Kernel 4: node model + residual, persistent. 128 rows/tile,
// 256 threads, 2 CTAs/SM (latency overlap). ldmatrix fragments.
// ---------------------------------------------------------------------------
#define N_B1   0
#define N_B2   8704
#define N_A    17408
#define N_NB2  26112
#define N_CINV 26240
#define NODE_SMEM_BYTES ((N_CINV + 128) * 4)   // 105,472 B
#define NODE_NTILES ((Nn + 127) / 128)          // 391

__launch_bounds__(256, 2)
__global__ void node_out_kernel(const float* __restrict__ nf,
                                const float* __restrict__ n_w1,
                                const float* __restrict__ n_w2,
                                const float* __restrict__ n_b2,
                                float* __restrict__ out)
{
    uint32_t* smw = (uint32_t*)dyn_smem;
    uint32_t* B1  = smw + N_B1;
    uint32_t* B2  = smw + N_B2;
    uint32_t* A   = smw + N_A;
    float*    NB2 = (float*)(smw + N_NB2);
    uint32_t* cinvh = smw + N_CINV;

    const int tid  = threadIdx.x;
    const int wid  = tid >> 5;      // 0..7
    const int lane = tid & 31;
    const int gid  = lane >> 2;
    const int tig  = lane & 3;

    if (tid < 128) NB2[tid] = n_b2[tid];
    for (int idx = tid; idx < 8192; idx += 256) {
        int n = idx >> 6, p = idx & 63, k0 = p << 1;
        B1[n * PWS + p] = pack_h2(n_w1[(128 + k0) * 128 + n],
                                  n_w1[(129 + k0) * 128 + n]);
        B2[n * PWS + p] = pack_h2(n_w2[k0 * 128 + n],
                                  n_w2[(k0 + 1) * 128 + n]);
    }

    const int m1 = wid * 16 + gid;
    const int m2 = m1 + 8;

    uint32_t aaddr, b1addr[2], b2addr[2];
    const uint32_t jstride = 8u * (PWS * 4);
    {
        int lsub = lane >> 3;
        int arow = wid * 16 + (lsub & 1) * 8 + (lane & 7);
        aaddr = (uint32_t)__cvta_generic_to_shared(A)
              + arow * (PWS * 4) + (lsub >> 1) * 16;
        for (int nfh = 0; nfh < 2; nfh++) {
            int brow = nfh * 64 + (lane & 7);
            uint32_t boff = brow * (PWS * 4) + (lsub & 1) * 16;
            b1addr[nfh] = (uint32_t)__cvta_generic_to_shared(B1) + boff;
            b2addr[nfh] = (uint32_t)__cvta_generic_to_shared(B2) + boff;
        }
    }

    for (int tile = blockIdx.x; tile < NODE_NTILES; tile += gridDim.x) {
        const int row0 = tile * 128;
        __syncthreads();
        if (tid < 128) {
            int row = row0 + tid;
            float ci = (row < Nn) ? 1.0f / fmaxf((float)g_cnt[row], 1.0f) : 0.0f;
            cinvh[tid] = pack_h2(ci, ci);
        }
        __syncthreads();

        for (int idx = tid; idx < 8192; idx += 256) {
            int m = idx >> 6, p = idx & 63;
            int row = row0 + m;
            uint32_t w = 0u;
            if (row < Nn) {
                uint32_t av = g_agg16[row * 64 + p];
                w = bitsh2(__hmul2(h2bits(av), h2bits(cinvh[m])));
            }
            A[m * PWS + p] = w;
        }
        __syncthreads();

        // GEMM1: both nfh halves per warp
        float acc[2][8][4];
#pragma unroll
        for (int h = 0; h < 2; h++)
#pragma unroll
            for (int j = 0; j < 8; j++)
#pragma unroll
                for (int q = 0; q < 4; q++) acc[h][j][q] = 0.0f;
#pragma unroll
        for (int ks = 0; ks < 8; ks++) {
            uint32_t a[4];
            ldsm_x4(a, aaddr + ks * 32);
#pragma unroll
            for (int h = 0; h < 2; h++)
#pragma unroll
                for (int j = 0; j < 8; j++) {
                    uint32_t b[2];
                    ldsm_x2(b, b1addr[h] + j * jstride + ks * 32);
                    mma16816h(acc[h][j], a, b);
                }
        }
        __syncthreads();

        const int row1 = row0 + m1, row2 = row0 + m2;
#pragma unroll
        for (int h = 0; h < 2; h++)
#pragma unroll
            for (int j = 0; j < 8; j++) {
                const int col = (h * 8 + j) * 8 + tig * 2;
                const int p = col >> 1;
                float2 pc1 = make_float2(0.0f, 0.0f), pc2 = make_float2(0.0f, 0.0f);
                if (row1 < Nn) pc1 = *(const float2*)(g_Pc + row1 * 128 + col);
                if (row2 < Nn) pc2 = *(const float2*)(g_Pc + row2 * 128 + col);
                A[m1 * PWS + p] = pack_h2(silu_f(acc[h][j][0] + pc1.x),
                                          silu_f(acc[h][j][1] + pc1.y));
                A[m2 * PWS + p] = pack_h2(silu_f(acc[h][j][2] + pc2.x),
                                          silu_f(acc[h][j][3] + pc2.y));
            }
        __syncthreads();

        // GEMM2 (reuse acc)
#pragma unroll
        for (int h = 0; h < 2; h++)
#pragma unroll
            for (int j = 0; j < 8; j++)
#pragma unroll
                for (int q = 0; q < 4; q++) acc[h][j][q] = 0.0f;
#pragma unroll
        for (int ks = 0; ks < 8; ks++) {
            uint32_t a[4];
            ldsm_x4(a, aaddr + ks * 32);
#pragma unroll
            for (int h = 0; h < 2; h++)
#pragma unroll
                for (int j = 0; j < 8; j++) {
                    uint32_t b[2];
                    ldsm_x2(b, b2addr[h] + j * jstride + ks * 32);
                    mma16816h(acc[h][j], a, b);
                }
        }

#pragma unroll
        for (int h = 0; h < 2; h++)
#pragma unroll
            for (int j = 0; j < 8; j++) {
                const int col = (h * 8 + j) * 8 + tig * 2;
                float b0 = NB2[col], b1 = NB2[col + 1];
                if (row1 < Nn) {
                    const float2 x = *(const float2*)(nf + row1 * 128 + col);
                    *(float2*)(out + row1 * 128 + col) =
                        make_float2(x.x + silu_f(acc[h][j][0] + b0),
                                    x.y + silu_f(acc[h][j][1] + b1));
                }
                if (row2 < Nn) {
                    const float2 x = *(const float2*)(nf + row2 * 128 + col);
                    *(float2*)(out + row2 * 128 + col) =
                        make_float2(x.x + silu_f(acc[h][j][2] + b0),
                                    x.y + silu_f(acc[h][j][3] + b1));
                }
            }
    }
}

// ---------------------------------------------------------------------------
extern "C" void kernel_launch(void* const* d_in, const int* in_sizes, int n_in,
                              void* d_out, int out_size)
{
    (void)in_sizes; (void)n_in; (void)out_size;
    const float* nf   = (const float*)d_in[0];
    const float* lat  = (const float*)d_in[2];
    const float* fd   = (const float*)d_in[3];
    const int*   ei   = (const int*)d_in[4];
    const int*   e2g  = (const int*)d_in[5];
    const float* e_w1 = (const float*)d_in[6];
    const float* e_b1 = (const float*)d_in[7];
    const float* e_w2 = (const float*)d_in[8];
    const float* e_b2 = (const float*)d_in[9];
    const float* n_w1 = (const float*)d_in[10];
    const float* n_b1 = (const float*)d_in[11];
    const float* n_w2 = (const float*)d_in[12];
    const float* n_b2 = (const float*)d_in[13];
    float* out = (float*)d_out;

    cudaFuncSetAttribute(prep_node_kernel,
                         cudaFuncAttributeMaxDynamicSharedMemorySize,
                         PREP_SMEM_BYTES);
    cudaFuncSetAttribute(edge_kernel,
                         cudaFuncAttributeMaxDynamicSharedMemorySize,
                         EDGE_SMEM_BYTES);
    cudaFuncSetAttribute(node_out_kernel,
                         cudaFuncAttributeMaxDynamicSharedMemorySize,
                         NODE_SMEM_BYTES);

    prep_node_kernel<<<148, 512, PREP_SMEM_BYTES>>>(nf, e_w1, n_w1, n_b1, lat, e_b1);
    edge_kernel<<<296, 256, EDGE_SMEM_BYTES>>>(fd, ei, e2g, e_w1, e_w2, e_b2);
    node_out_kernel<<<296, 256, NODE_SMEM_BYTES>>>(nf, n_w1, n_w2, n_b2, out);
}

// round 17
// speedup vs baseline: 1.1087x; 1.1087x over previous
#include <cuda_runtime.h>
#include <cuda_fp16.h>
#include <cstdint>
#include <cstring>

#define Nn 50000
#define Ee 800000
#define Gg 2048
#define Hh 128

extern __shared__ char dyn_smem[];

// ---------------- device scratch ----------
__device__ uint32_t g_Pa16[Nn * 64];   // fp16x2: nf @ e_w1[0:128]
__device__ uint32_t g_Pb16[Nn * 64];   // fp16x2: nf @ e_w1[128:256]
__device__ uint32_t g_Qb16[Gg * 64];   // fp16x2: lat @ e_w1[256:262] + e_b1
__device__ float    g_Pc[Nn * Hh];     // fp32:   nf @ n_w1[0:128] + n_b1
__device__ uint32_t g_agg16[Nn * 64];  // fp16x2 scatter-sum accumulator
__device__ int      g_cnt[Nn];         // per-node edge count

__device__ __forceinline__ float silu_f(float x) {
    float t;
    asm("tanh.approx.f32 %0, %1;" : "=f"(t) : "f"(0.5f * x));
    return 0.5f * x * (1.0f + t);
}

__device__ __forceinline__ uint32_t pack_h2(float v0, float v1) {
    __half2 h = __floats2half2_rn(v0, v1);
    uint32_t u;
    memcpy(&u, &h, 4);
    return u;
}

__device__ __forceinline__ __half2 h2bits(uint32_t u) {
    __half2 h; memcpy(&h, &u, 4); return h;
}
__device__ __forceinline__ uint32_t bitsh2(__half2 h) {
    uint32_t u; memcpy(&u, &h, 4); return u;
}

__device__ __forceinline__ __half2 silu_h2(__half2 x) {
    __half2 h = __hmul2(x, __float2half2_rn(0.5f));
    uint32_t hb = bitsh2(h), tb;
    asm("tanh.approx.f16x2 %0, %1;" : "=r"(tb) : "r"(hb));
    __half2 t = h2bits(tb);
    return __hfma2(h, t, h);
}

__device__ __forceinline__ void mma16816h(float* d, const uint32_t* a, const uint32_t* b) {
    asm volatile(
        "mma.sync.aligned.m16n8k16.row.col.f32.f16.f16.f32 "
        "{%0,%1,%2,%3}, {%4,%5,%6,%7}, {%8,%9}, {%0,%1,%2,%3};"
        : "+f"(d[0]), "+f"(d[1]), "+f"(d[2]), "+f"(d[3])
        : "r"(a[0]), "r"(a[1]), "r"(a[2]), "r"(a[3]), "r"(b[0]), "r"(b[1]));
}

__device__ __forceinline__ void ldsm_x4(uint32_t* r, uint32_t saddr) {
    asm volatile("ldmatrix.sync.aligned.m8n8.x4.shared.b16 {%0,%1,%2,%3}, [%4];"
        : "=r"(r[0]), "=r"(r[1]), "=r"(r[2]), "=r"(r[3]) : "r"(saddr));
}
__device__ __forceinline__ void ldsm_x2(uint32_t* r, uint32_t saddr) {
    asm volatile("ldmatrix.sync.aligned.m8n8.x2.shared.b16 {%0,%1}, [%2];"
        : "=r"(r[0]), "=r"(r[1]) : "r"(saddr));
}

// vectorized fp16x2 global reduction (4 halves per op)
__device__ __forceinline__ void red2_h2(uint32_t* p, uint32_t a, uint32_t b) {
    asm volatile("red.global.add.noftz.v2.f16x2 [%0], {%1, %2};"
                 :: "l"(p), "r"(a), "r"(b) : "memory");
}

#define PWS 68   // plane word-stride per row (64 pair-words + 4 pad)

// ---------------------------------------------------------------------------
// Kernel 1: persistent Pa/Pb (fp16) + Pc (fp32) + Qb (fp16, folded) precompute
// + zero agg/cnt. ldmatrix fragment loads.
// ---------------------------------------------------------------------------
#define P_B0  0
#define P_B1  8704
#define P_B2  17408
#define P_A   26112
#define P_NB1 34816
#define PREP_SMEM_BYTES ((P_NB1 + 128) * 4)   // 139,776 B
#define PREP_NTILES ((Nn + 127) / 128)         // 391

__launch_bounds__(512, 1)
__global__ void prep_node_kernel(const float* __restrict__ nf,
                                 const float* __restrict__ e_w1,
                                 const float* __restrict__ n_w1,
                                 const float* __restrict__ n_b1,
                                 const float* __restrict__ lat,
                                 const float* __restrict__ e_b1)
{
    uint32_t* smw = (uint32_t*)dyn_smem;
    uint32_t* Bp[3] = {smw + P_B0, smw + P_B1, smw + P_B2};
    uint32_t* A   = smw + P_A;
    float*    NB1 = (float*)(smw + P_NB1);

    const int tid  = threadIdx.x;
    const int wid  = tid >> 5;
    const int lane = tid & 31;
    const int gid  = lane >> 2;
    const int tig  = lane & 3;

    // folded prep_graph: Qb = lat @ e_w1[256:262] + e_b1 -> fp16x2
    for (int idx = blockIdx.x * 512 + tid; idx < Gg * 64; idx += gridDim.x * 512) {
        int g = idx >> 6, c0 = (idx & 63) * 2;
        float a0 = e_b1[c0], a1 = e_b1[c0 + 1];
#pragma unroll
        for (int k = 0; k < 6; k++) {
            float lv = lat[g * 6 + k];
            a0 += lv * e_w1[(256 + k) * 128 + c0];
            a1 += lv * e_w1[(256 + k) * 128 + c0 + 1];
        }
        g_Qb16[idx] = pack_h2(a0, a1);
    }

    if (tid < 128) NB1[tid] = n_b1[tid];
    for (int blk = 0; blk < 3; blk++) {
        const float* bsrc = (blk == 0) ? e_w1
                          : (blk == 1) ? (e_w1 + 128 * 128)
                                       : n_w1;
        uint32_t* B = Bp[blk];
        for (int idx = tid; idx < 8192; idx += 512) {
            int n = idx >> 6, p = idx & 63, k0 = p << 1;
            B[n * PWS + p] = pack_h2(bsrc[k0 * 128 + n], bsrc[(k0 + 1) * 128 + n]);
        }
    }

    const int rg  = wid >> 1;
    const int nfh = wid & 1;
    const int m1  = rg * 16 + gid;

    uint32_t aaddr, baddr0[3];
    const uint32_t jstride = 8u * (PWS * 4);
    {
        int lsub = lane >> 3;
        int arow = rg * 16 + (lsub & 1) * 8 + (lane & 7);
        aaddr = (uint32_t)__cvta_generic_to_shared(A)
              + arow * (PWS * 4) + (lsub >> 1) * 16;
        int brow = nfh * 64 + (lane & 7);
        uint32_t boff = brow * (PWS * 4) + (lsub & 1) * 16;
        for (int blk = 0; blk < 3; blk++)
            baddr0[blk] = (uint32_t)__cvta_generic_to_shared(Bp[blk]) + boff;
    }

    for (int tile = blockIdx.x; tile < PREP_NTILES; tile += gridDim.x) {
        const int row0 = tile * 128;
        __syncthreads();
        if (tid < 128 && row0 + tid < Nn) g_cnt[row0 + tid] = 0;
        for (int idx = tid; idx < 8192; idx += 512) {
            int m = idx >> 6, p = idx & 63, c0 = p << 1;
            int row = row0 + m;
            float v0 = 0.0f, v1 = 0.0f;
            if (row < Nn) {
                const float2 v = *(const float2*)(nf + row * 128 + c0);
                v0 = v.x; v1 = v.y;
                g_agg16[row * 64 + p] = 0u;
            }
            A[m * PWS + p] = pack_h2(v0, v1);
        }
        __syncthreads();

        const int row1 = row0 + m1, row2 = row1 + 8;
        for (int blk = 0; blk < 3; blk++) {
            float acc[8][4];
#pragma unroll
            for (int j = 0; j < 8; j++)
#pragma unroll
                for (int q = 0; q < 4; q++) acc[j][q] = 0.0f;

#pragma unroll
            for (int ks = 0; ks < 8; ks++) {
                uint32_t a[4];
                ldsm_x4(a, aaddr + ks * 32);
#pragma unroll
                for (int j = 0; j < 8; j++) {
                    uint32_t b[2];
                    ldsm_x2(b, baddr0[blk] + j * jstride + ks * 32);
                    mma16816h(acc[j], a, b);
                }
            }

            if (blk < 2) {
                uint32_t* dst16 = (blk == 0) ? g_Pa16 : g_Pb16;
#pragma unroll
                for (int j = 0; j < 8; j++) {
                    const int col = (nfh * 8 + j) * 8 + tig * 2;
                    const int pw = col >> 1;
                    if (row1 < Nn) dst16[row1 * 64 + pw] = pack_h2(acc[j][0], acc[j][1]);
                    if (row2 < Nn) dst16[row2 * 64 + pw] = pack_h2(acc[j][2], acc[j][3]);
                }
            } else {
#pragma unroll
                for (int j = 0; j < 8; j++) {
                    const int col = (nfh * 8 + j) * 8 + tig * 2;
                    float b0 = NB1[col], b1 = NB1[col + 1];
                    if (row1 < Nn)
                        *(float2*)(g_Pc + row1 * 128 + col) =
                            make_float2(acc[j][0] + b0, acc[j][1] + b1);
                    if (row2 < Nn)
                        *(float2*)(g_Pc + row2 * 128 + col) =
                            make_float2(acc[j][2] + b0, acc[j][3] + b1);
                }
            }
        }
    }
}

// ---------------------------------------------------------------------------
// Kernel 3: fused edge pipeline. 128 edges/tile, 256 threads, 2 CTAs/SM.
// Phase A: line-coalesced gather; MMA: ldmatrix;
// epilogue: h2 silu + shfl-pair + red.v2.f16x2 (R15 version).
// ---------------------------------------------------------------------------
#define TILE_M 128
#define EDGE_NTILES (Ee / TILE_M)      // 6250

#define O_SRC   0
#define O_DST   128
#define O_GS    256
#define O_FDS   384
#define O_A     768
#define O_B     (O_A + 128 * PWS)
#define EDGE_SMEM_BYTES ((O_B + 128 * PWS) * 4)   // 72,704 B

__launch_bounds__(256, 2)
__global__ void edge_kernel(const float* __restrict__ frac_diff,
                            const int*   __restrict__ ei,
                            const int*   __restrict__ e2g,
                            const float* __restrict__ e_w1,
                            const float* __restrict__ e_w2,
                            const float* __restrict__ e_b2)
{
    uint32_t* smw = (uint32_t*)dyn_smem;
    int*   srcs = (int*)(smw + O_SRC);
    int*   dsts = (int*)(smw + O_DST);
    int*   gs   = (int*)(smw + O_GS);
    float* fds  = (float*)(smw + O_FDS);
    uint32_t* A = smw + O_A;
    uint32_t* B = smw + O_B;

    const int tid  = threadIdx.x;
    const int wid  = tid >> 5;
    const int lane = tid & 31;
    const int gid  = lane >> 2;
    const int tig  = lane & 3;
    const int wr   = wid >> 2;
    const int wc   = wid & 3;

    uint32_t b2h[4];
#pragma unroll
    for (int nfr = 0; nfr < 4; nfr++) {
        const int c0 = wc * 32 + nfr * 8 + tig * 2;
        b2h[nfr] = pack_h2(e_b2[c0], e_b2[c0 + 1]);
    }

    const int wordpos = (lane & 15) * 4;
    const int rsel    = lane >> 4;
    uint32_t w1dc[3][4];
#pragma unroll
    for (int k = 0; k < 3; k++)
#pragma unroll
        for (int j = 0; j < 4; j++) {
            int c = (wordpos + j) * 2;
            w1dc[k][j] = pack_h2(e_w1[(262 + k) * 128 + c],
                                 e_w1[(262 + k) * 128 + c + 1]);
        }

    for (int idx = tid; idx < 8192; idx += 256) {
        int n = idx >> 6, p = idx & 63, k0 = p << 1;
        B[n * PWS + p] = pack_h2(e_w2[k0 * 128 + n], e_w2[(k0 + 1) * 128 + n]);
    }

    uint32_t aaddr[4], baddr[4];
    {
        uint32_t A_s = (uint32_t)__cvta_generic_to_shared(A);
        uint32_t B_s = (uint32_t)__cvta_generic_to_shared(B);
        int lsub = lane >> 3;
#pragma unroll
        for (int mf = 0; mf < 4; mf++) {
            int arow = wr * 64 + mf * 16 + (lsub & 1) * 8 + (lane & 7);
            aaddr[mf] = A_s + arow * (PWS * 4) + (lsub >> 1) * 16;
        }
        int bsub = lsub & 1;
#pragma unroll
        for (int nfr = 0; nfr < 4; nfr++) {
            int brow = wc * 32 + nfr * 8 + (lane & 7);
            baddr[nfr] = B_s + brow * (PWS * 4) + bsub * 16;
        }
    }

    for (int tile = blockIdx.x; tile < EDGE_NTILES; tile += gridDim.x) {
        __syncthreads();
        const int e0 = tile * TILE_M;
        if (tid < 128) {
            int e = e0 + tid;
            int s = ei[e];
            srcs[tid] = s;
            dsts[tid] = ei[Ee + e];
            gs[tid]   = e2g[e];
            atomicAdd(&g_cnt[s], 1);
        }
        for (int i = tid; i < 384; i += 256) fds[i] = frac_diff[e0 * 3 + i];
        __syncthreads();

        // Phase A: line-coalesced gather + h2 combine + silu
#pragma unroll
        for (int it = 0; it < 8; it++) {
            const int m = wid * 16 + it * 2 + rsel;
            const int sA = srcs[m], dAi = dsts[m], gA = gs[m];
            const __half2 f0h = __float2half2_rn(fds[m * 3 + 0]);
            const __half2 f1h = __float2half2_rn(fds[m * 3 + 1]);
            const __half2 f2h = __float2half2_rn(fds[m * 3 + 2]);
            uint4 pa = *(const uint4*)(g_Pa16 + sA * 64 + wordpos);
            uint4 pb = *(const uint4*)(g_Pb16 + dAi * 64 + wordpos);
            uint4 qb = *(const uint4*)(g_Qb16 + gA * 64 + wordpos);
            uint32_t paw[4] = {pa.x, pa.y, pa.z, pa.w};
            uint32_t pbw[4] = {pb.x, pb.y, pb.z, pb.w};
            uint32_t qbw[4] = {qb.x, qb.y, qb.z, qb.w};
            uint32_t ow[4];
#pragma unroll
            for (int j = 0; j < 4; j++) {
                __half2 x = __hadd2(h2bits(paw[j]), h2bits(pbw[j]));
                x = __hadd2(x, h2bits(qbw[j]));
                x = __hfma2(f0h, h2bits(w1dc[0][j]), x);
                x = __hfma2(f1h, h2bits(w1dc[1][j]), x);
                x = __hfma2(f2h, h2bits(w1dc[2][j]), x);
                ow[j] = bitsh2(silu_h2(x));
            }
            uint4 outw;
            outw.x = ow[0]; outw.y = ow[1]; outw.z = ow[2]; outw.w = ow[3];
            *(uint4*)(A + m * PWS + wordpos) = outw;
        }
        __syncthreads();

        // MMA: ldmatrix fragments
        float acc[4][4][4];
#pragma unroll
        for (int mf = 0; mf < 4; mf++)
#pragma unroll
            for (int nfr = 0; nfr < 4; nfr++)
#pragma unroll
                for (int q = 0; q < 4; q++) acc[mf][nfr][q] = 0.0f;

#pragma unroll
        for (int ks = 0; ks < 8; ks++) {
            uint32_t b[4][2];
#pragma unroll
            for (int nfr = 0; nfr < 4; nfr++)
                ldsm_x2(b[nfr], baddr[nfr] + ks * 32);
#pragma unroll
            for (int mf = 0; mf < 4; mf++) {
                uint32_t a[4];
                ldsm_x4(a, aaddr[mf] + ks * 32);
#pragma unroll
                for (int nfr = 0; nfr < 4; nfr++)
                    mma16816h(acc[mf][nfr], a, b[nfr]);
            }
        }

        // Epilogue: h2 bias+silu, shfl-pair, red.v2.f16x2 into g_agg16
        const bool evn = ((tig & 1) == 0);
#pragma unroll
        for (int mf = 0; mf < 4; mf++) {
            const int m1 = wr * 64 + mf * 16 + gid;
            uint32_t* agg1 = g_agg16 + srcs[m1] * 64;
            uint32_t* agg2 = g_agg16 + srcs[m1 + 8] * 64;
#pragma unroll
            for (int nfr = 0; nfr < 4; nfr++) {
                const int c0 = wc * 32 + nfr * 8 + tig * 2;
                __half2 hA = __floats2half2_rn(acc[mf][nfr][0], acc[mf][nfr][1]);
                __half2 hB = __floats2half2_rn(acc[mf][nfr][2], acc[mf][nfr][3]);
                hA = silu_h2(__hadd2(hA, h2bits(b2h[nfr])));
                hB = silu_h2(__hadd2(hB, h2bits(b2h[nfr])));
                uint32_t wA = bitsh2(hA), wB = bitsh2(hB);
                uint32_t tA = __shfl_xor_sync(0xFFFFFFFFu, wA, 1);
                uint32_t tB = __shfl_xor_sync(0xFFFFFFFFu, wB, 1);
                if (evn) red2_h2(agg1 + (c0 >> 1), wA, tA);           // row m1
                else     red2_h2(agg2 + ((c0 - 2) >> 1), tB, wB);     // row m1+8
            }
        }
    }
}

// ---------------------------------------------------------------------------
// Kernel 4: node model + residual, persistent. 128 rows/tile, 512 thr x 1 CTA.
// ldmatrix fragment loads for both GEMMs. (R15 version)
// ---------------------------------------------------------------------------
#define N_B1   0
#define N_B2   8704
#define N_A    17408
#define N_NB2  26112
#define N_CINV 26240
#define NODE_SMEM_BYTES ((N_CINV + 128) * 4)   // 105,472 B
#define NODE_NTILES ((Nn + 127) / 128)          // 391

__launch_bounds__(512, 1)
__global__ void node_out_kernel(const float* __restrict__ nf,
                                const float* __restrict__ n_w1,
                                const float* __restrict__ n_w2,
                                const float* __restrict__ n_b2,
                                float* __restrict__ out)
{
    uint32_t* smw = (uint32_t*)dyn_smem;
    uint32_t* B1  = smw + N_B1;
    uint32_t* B2  = smw + N_B2;
    uint32_t* A   = smw + N_A;
    float*    NB2 = (float*)(smw + N_NB2);
    uint32_t* cinvh = smw + N_CINV;

    const int tid  = threadIdx.x;
    const int wid  = tid >> 5;
    const int lane = tid & 31;
    const int gid  = lane >> 2;
    const int tig  = lane & 3;

    if (tid < 128) NB2[tid] = n_b2[tid];
    for (int idx = tid; idx < 8192; idx += 512) {
        int n = idx >> 6, p = idx & 63, k0 = p << 1;
        B1[n * PWS + p] = pack_h2(n_w1[(128 + k0) * 128 + n],
                                  n_w1[(129 + k0) * 128 + n]);
        B2[n * PWS + p] = pack_h2(n_w2[k0 * 128 + n],
                                  n_w2[(k0 + 1) * 128 + n]);
    }

    const int rg  = wid >> 1;
    const int nfh = wid & 1;
    const int m1  = rg * 16 + gid;
    const int m2  = m1 + 8;

    uint32_t aaddr, b1addr, b2addr;
    const uint32_t jstride = 8u * (PWS * 4);
    {
        int lsub = lane >> 3;
        int arow = rg * 16 + (lsub & 1) * 8 + (lane & 7);
        aaddr = (uint32_t)__cvta_generic_to_shared(A)
              + arow * (PWS * 4) + (lsub >> 1) * 16;
        int brow = nfh * 64 + (lane & 7);
        uint32_t boff = brow * (PWS * 4) + (lsub & 1) * 16;
        b1addr = (uint32_t)__cvta_generic_to_shared(B1) + boff;
        b2addr = (uint32_t)__cvta_generic_to_shared(B2) + boff;
    }

    for (int tile = blockIdx.x; tile < NODE_NTILES; tile += gridDim.x) {
        const int row0 = tile * 128;
        __syncthreads();
        if (tid < 128) {
            int row = row0 + tid;
            float ci = (row < Nn) ? 1.0f / fmaxf((float)g_cnt[row], 1.0f) : 0.0f;
            cinvh[tid] = pack_h2(ci, ci);
        }
        __syncthreads();

        for (int idx = tid; idx < 8192; idx += 512) {
            int m = idx >> 6, p = idx & 63;
            int row = row0 + m;
            uint32_t w = 0u;
            if (row < Nn) {
                uint32_t av = g_agg16[row * 64 + p];
                w = bitsh2(__hmul2(h2bits(av), h2bits(cinvh[m])));
            }
            A[m * PWS + p] = w;
        }
        __syncthreads();

        float acc[8][4];
#pragma unroll
        for (int j = 0; j < 8; j++)
#pragma unroll
            for (int q = 0; q < 4; q++) acc[j][q] = 0.0f;
#pragma unroll
        for (int ks = 0; ks < 8; ks++) {
            uint32_t a[4];
            ldsm_x4(a, aaddr + ks * 32);
#pragma unroll
            for (int j = 0; j < 8; j++) {
                uint32_t b[2];
                ldsm_x2(b, b1addr + j * jstride + ks * 32);
                mma16816h(acc[j], a, b);
            }
        }
        __syncthreads();

        const int row1 = row0 + m1, row2 = row0 + m2;
#pragma unroll
        for (int j = 0; j < 8; j++) {
            const int col = (nfh * 8 + j) * 8 + tig * 2;
            const int p = col >> 1;
            float2 pc1 = make_float2(0.0f, 0.0f), pc2 = make_float2(0.0f, 0.0f);
            if (row1 < Nn) pc1 = *(const float2*)(g_Pc + row1 * 128 + col);
            if (row2 < Nn) pc2 = *(const float2*)(g_Pc + row2 * 128 + col);
            A[m1 * PWS + p] = pack_h2(silu_f(acc[j][0] + pc1.x),
                                      silu_f(acc[j][1] + pc1.y));
            A[m2 * PWS + p] = pack_h2(silu_f(acc[j][2] + pc2.x),
                                      silu_f(acc[j][3] + pc2.y));
        }
        __syncthreads();

        float acc2[8][4];
#pragma unroll
        for (int j = 0; j < 8; j++)
#pragma unroll
            for (int q = 0; q < 4; q++) acc2[j][q] = 0.0f;
#pragma unroll
        for (int ks = 0; ks < 8; ks++) {
            uint32_t a[4];
            ldsm_x4(a, aaddr + ks * 32);
#pragma unroll
            for (int j = 0; j < 8; j++) {
                uint32_t b[2];
                ldsm_x2(b, b2addr + j * jstride + ks * 32);
                mma16816h(acc2[j], a, b);
            }
        }

#pragma unroll
        for (int j = 0; j < 8; j++) {
            const int col = (nfh * 8 + j) * 8 + tig * 2;
            float b0 = NB2[col], b1 = NB2[col + 1];
            if (row1 < Nn) {
                const float2 x = *(const float2*)(nf + row1 * 128 + col);
                *(float2*)(out + row1 * 128 + col) =
                    make_float2(x.x + silu_f(acc2[j][0] + b0),
                                x.y + silu_f(acc2[j][1] + b1));
            }
            if (row2 < Nn) {
                const float2 x = *(const float2*)(nf + row2 * 128 + col);
                *(float2*)(out + row2 * 128 + col) =
                    make_float2(x.x + silu_f(acc2[j][2] + b0),
                                x.y + silu_f(acc2[j][3] + b1));
            }
        }
    }
}

// ---------------------------------------------------------------------------
extern "C" void kernel_launch(void* const* d_in, const int* in_sizes, int n_in,
                              void* d_out, int out_size)
{
    (void)in_sizes; (void)n_in; (void)out_size;
    const float* nf   = (const float*)d_in[0];
    const float* lat  = (const float*)d_in[2];
    const float* fd   = (const float*)d_in[3];
    const int*   ei   = (const int*)d_in[4];
    const int*   e2g  = (const int*)d_in[5];
    const float* e_w1 = (const float*)d_in[6];
    const float* e_b1 = (const float*)d_in[7];
    const float* e_w2 = (const float*)d_in[8];
    const float* e_b2 = (const float*)d_in[9];
    const float* n_w1 = (const float*)d_in[10];
    const float* n_b1 = (const float*)d_in[11];
    const float* n_w2 = (const float*)d_in[12];
    const float* n_b2 = (const float*)d_in[13];
    float* out = (float*)d_out;

    cudaFuncSetAttribute(prep_node_kernel,
                         cudaFuncAttributeMaxDynamicSharedMemorySize,
                         PREP_SMEM_BYTES);
    cudaFuncSetAttribute(edge_kernel,
                         cudaFuncAttributeMaxDynamicSharedMemorySize,
                         EDGE_SMEM_BYTES);
    cudaFuncSetAttribute(node_out_kernel,
                         cudaFuncAttributeMaxDynamicSharedMemorySize,
                         NODE_SMEM_BYTES);

    prep_node_kernel<<<148, 512, PREP_SMEM_BYTES>>>(nf, e_w1, n_w1, n_b1, lat, e_b1);
    edge_kernel<<<296, 256, EDGE_SMEM_BYTES>>>(fd, ei, e2g, e_w1, e_w2, e_b2);
    node_out_kernel<<<148, 512, NODE_SMEM_BYTES>>>(nf, n_w1, n_w2, n_b2, out);
}